// round 1
// baseline (speedup 1.0000x reference)
#include <cuda_runtime.h>
#include <cuda_bf16.h>

// Problem constants
// B=16, K=32, H=W=28, HID=64, OUT=64, NOPS=8
// N = B*K = 512 images

#define NIMG 512

// ---------------- scratch (device globals: no allocation allowed) -------------
__device__ float g_h1p[NIMG * 32 * 14 * 14];   // conv1+relu+pool out  (12.8 MB)
__device__ float g_h2p[NIMG * 64 * 7 * 7];     // conv2+relu+pool out  (6.4 MB)
__device__ float g_feat[NIMG * 64];            // fc+relu out          (128 KB)
__device__ float g_wt[8 * 64 * 64];            // eq_w transposed: [o][d*64+e]
__device__ float g_part[NIMG * 64];            // per-(b,k) partial relu-sums

// ---------------- kernel 0: transpose eq_w for coalesced per-block reads ------
__global__ void k_prep(const float* __restrict__ eq_w) {
    int gid = blockIdx.x * blockDim.x + threadIdx.x;
    int nth = gridDim.x * blockDim.x;
    for (int idx = gid; idx < 8 * 64 * 64; idx += nth) {
        int o = idx & 7;
        int de = idx >> 3;                       // d*64 + e
        g_wt[o * 4096 + de] = eq_w[idx];
    }
}

// ---------------- kernel 1: conv1(1->32,3x3,SAME) + relu + maxpool2 -----------
__global__ void __launch_bounds__(256) k_conv1(const float* __restrict__ x,
                                               const float* __restrict__ w,
                                               const float* __restrict__ bias) {
    __shared__ float smin[28 * 28];
    __shared__ float smw[32 * 9];
    __shared__ float smb[32];
    int n = blockIdx.x;
    int tid = threadIdx.x;
    for (int idx = tid; idx < 784; idx += 256) smin[idx] = x[n * 784 + idx];
    for (int idx = tid; idx < 288; idx += 256) smw[idx] = w[idx];
    if (tid < 32) smb[tid] = bias[tid];
    __syncthreads();

    for (int idx = tid; idx < 32 * 196; idx += 256) {
        int c = idx / 196;
        int pix = idx % 196;
        int oy = pix / 14, ox = pix % 14;
        float patch[4][4];
#pragma unroll
        for (int r = 0; r < 4; r++) {
            int y = oy * 2 - 1 + r;
#pragma unroll
            for (int cc = 0; cc < 4; cc++) {
                int xx = ox * 2 - 1 + cc;
                patch[r][cc] = (y >= 0 && y < 28 && xx >= 0 && xx < 28)
                                   ? smin[y * 28 + xx] : 0.f;
            }
        }
        float b0 = smb[c];
        float s00 = b0, s01 = b0, s10 = b0, s11 = b0;
        const float* wp = smw + c * 9;
#pragma unroll
        for (int ky = 0; ky < 3; ky++)
#pragma unroll
            for (int kx = 0; kx < 3; kx++) {
                float wv = wp[ky * 3 + kx];
                s00 = fmaf(patch[ky][kx],     wv, s00);
                s01 = fmaf(patch[ky][kx + 1], wv, s01);
                s10 = fmaf(patch[ky + 1][kx],     wv, s10);
                s11 = fmaf(patch[ky + 1][kx + 1], wv, s11);
            }
        float m = fmaxf(fmaxf(s00, s01), fmaxf(s10, s11));
        g_h1p[n * 6272 + idx] = fmaxf(m, 0.f);
    }
}

// ---------------- kernel 2: conv2(32->64,3x3,SAME) + relu + maxpool2 ----------
// dynamic smem: input 32*196 (25088 B) + weights 64*32*9 (73728 B) + bias (256 B)
__global__ void __launch_bounds__(256) k_conv2(const float* __restrict__ w,
                                               const float* __restrict__ bias) {
    extern __shared__ float sm[];
    float* smin = sm;              // 6272
    float* smw  = sm + 6272;       // 18432
    float* smb  = sm + 6272 + 18432;
    int n = blockIdx.x;
    int tid = threadIdx.x;
    for (int idx = tid; idx < 6272; idx += 256) smin[idx] = g_h1p[n * 6272 + idx];
    for (int idx = tid; idx < 18432; idx += 256) smw[idx] = w[idx];
    if (tid < 64) smb[tid] = bias[tid];
    __syncthreads();

    for (int idx = tid; idx < 64 * 49; idx += 256) {
        int co = idx / 49;
        int pix = idx % 49;
        int oy = pix / 7, ox = pix % 7;
        float b0 = smb[co];
        float s00 = b0, s01 = b0, s10 = b0, s11 = b0;
        for (int ci = 0; ci < 32; ci++) {
            const float* ip = smin + ci * 196;
            const float* wp = smw + (co * 32 + ci) * 9;
            float patch[4][4];
#pragma unroll
            for (int r = 0; r < 4; r++) {
                int y = oy * 2 - 1 + r;
#pragma unroll
                for (int cc = 0; cc < 4; cc++) {
                    int xx = ox * 2 - 1 + cc;
                    patch[r][cc] = (y >= 0 && y < 14 && xx >= 0 && xx < 14)
                                       ? ip[y * 14 + xx] : 0.f;
                }
            }
#pragma unroll
            for (int ky = 0; ky < 3; ky++)
#pragma unroll
                for (int kx = 0; kx < 3; kx++) {
                    float wv = wp[ky * 3 + kx];
                    s00 = fmaf(patch[ky][kx],     wv, s00);
                    s01 = fmaf(patch[ky][kx + 1], wv, s01);
                    s10 = fmaf(patch[ky + 1][kx],     wv, s10);
                    s11 = fmaf(patch[ky + 1][kx + 1], wv, s11);
                }
        }
        float m = fmaxf(fmaxf(s00, s01), fmaxf(s10, s11));
        g_h2p[n * 3136 + idx] = fmaxf(m, 0.f);
    }
}

// ---------------- kernel 3: fc (512x3136 @ 3136x64^T) + relu ------------------
// 64 blocks x 8 images; images in smem; fc_w streamed once per block (L2-hot).
__global__ void __launch_bounds__(256) k_fc(const float* __restrict__ fcw,
                                            const float* __restrict__ fcb) {
    extern __shared__ float sm[];  // 8 * 3136
    int n0 = blockIdx.x * 8;
    int tid = threadIdx.x, warp = tid >> 5, lane = tid & 31;
    for (int idx = tid; idx < 8 * 3136; idx += 256) sm[idx] = g_h2p[n0 * 3136 + idx];
    __syncthreads();

    for (int h = warp; h < 64; h += 8) {
        float acc[8] = {0, 0, 0, 0, 0, 0, 0, 0};
        const float* wrow = fcw + h * 3136;
        for (int kk = lane; kk < 3136; kk += 32) {   // 98 iterations
            float wv = wrow[kk];
#pragma unroll
            for (int im = 0; im < 8; im++)
                acc[im] = fmaf(wv, sm[im * 3136 + kk], acc[im]);
        }
        float bh = fcb[h];
#pragma unroll
        for (int im = 0; im < 8; im++) {
            float v = acc[im];
#pragma unroll
            for (int off = 16; off; off >>= 1)
                v += __shfl_down_sync(0xffffffffu, v, off);
            if (lane == 0)
                g_feat[(n0 + im) * 64 + h] = fmaxf(v + bh, 0.f);
        }
    }
}

// ---------------- kernel 4: equivariant block ---------------------------------
// One block per (b,k) pair (512 blocks). For fixed (b,k):
//   x6[e,i,j] = sum_d a_i a_j WK[d,e] + ROW[i,e] + COL[j,e] + R[e]
// with  WK  = a_k*W0 + s*W3
//       ROW = A @ (s*(a_k*W2 + s*W6))       (W6 term from m_jk, i-dependent)
//       COL = A @ (s*(a_k*W1 + s*W5))       (W5 term from m_ik, j-dependent)
//       R   = sum_d s^2*(a_k*W4 + s*W7) + eq_b
// Output: per-block sum over (i,j) of relu(x6), written to g_part[block][e].
__global__ void __launch_bounds__(256) k_eq(const float* __restrict__ eq_b) {
    extern __shared__ float sm[];
    float* A   = sm;            // 2048  : feat rows of batch b, [i*64+d]
    float* WK  = sm + 2048;     // 64*68 : transposed + padded, [e*68+d]
    float* T   = sm + 6400;     // 4096  : temp matrix, [d*64+e]
    float* ROW = sm + 10496;    // 2048
    float* COL = sm + 12544;    // 2048
    float* S   = sm + 14592;    // 64
    float* R   = sm + 14656;    // 64
    float* C   = sm + 14720;    // 8*64 per-warp pair-product / partial sums
    // total 15232 floats = 60928 B

    int b = blockIdx.x >> 5;
    int k = blockIdx.x & 31;
    int tid = threadIdx.x;

    const float* W0 = g_wt;
    const float* W1 = g_wt + 1 * 4096;
    const float* W2 = g_wt + 2 * 4096;
    const float* W3 = g_wt + 3 * 4096;
    const float* W4 = g_wt + 4 * 4096;
    const float* W5 = g_wt + 5 * 4096;
    const float* W6 = g_wt + 6 * 4096;
    const float* W7 = g_wt + 7 * 4096;

    for (int idx = tid; idx < 2048; idx += 256) A[idx] = g_feat[b * 2048 + idx];
    __syncthreads();

    if (tid < 64) {
        float acc = 0.f;
#pragma unroll
        for (int i = 0; i < 32; i++) acc += A[i * 64 + tid];
        S[tid] = acc * (1.f / 32.f);
    }
    __syncthreads();

    const float* ak = A + k * 64;

    // WK (transposed) and T = Mrow
    for (int idx = tid; idx < 4096; idx += 256) {
        int d = idx >> 6, e = idx & 63;
        float sd = S[d], a = ak[d];
        WK[e * 68 + d] = fmaf(a, W0[idx], sd * W3[idx]);
        T[idx]         = sd * fmaf(a, W2[idx], sd * W6[idx]);
    }
    if (tid < 64) {
        float acc = 0.f;
        for (int d = 0; d < 64; d++) {
            float sd = S[d];
            acc += sd * sd * fmaf(ak[d], W4[d * 64 + tid], sd * W7[d * 64 + tid]);
        }
        R[tid] = acc + eq_b[tid];
    }
    __syncthreads();

    // ROW = A @ T
    for (int idx = tid; idx < 2048; idx += 256) {
        int i = idx >> 6, e = idx & 63;
        float acc = 0.f;
#pragma unroll 8
        for (int d = 0; d < 64; d++) acc = fmaf(A[i * 64 + d], T[d * 64 + e], acc);
        ROW[idx] = acc;
    }
    __syncthreads();

    // T = Mcol
    for (int idx = tid; idx < 4096; idx += 256) {
        int d = idx >> 6;
        float sd = S[d];
        T[idx] = sd * fmaf(ak[d], W1[idx], sd * W5[idx]);
    }
    __syncthreads();

    // COL = A @ T
    for (int idx = tid; idx < 2048; idx += 256) {
        int j = idx >> 6, e = idx & 63;
        float acc = 0.f;
#pragma unroll 8
        for (int d = 0; d < 64; d++) acc = fmaf(A[j * 64 + d], T[d * 64 + e], acc);
        COL[idx] = acc;
    }
    __syncthreads();

    // main loop: 1024 (i,j) pairs, 8 warps, each warp owns 64 e-channels
    int warp = tid >> 5, lane = tid & 31;
    float* cw = C + warp * 64;
    float sum0 = 0.f, sum1 = 0.f;
    const float4* wk0 = (const float4*)(WK + lane * 68);
    const float4* wk1 = (const float4*)(WK + (lane + 32) * 68);

    for (int p = warp; p < 1024; p += 8) {
        int i = p >> 5, j = p & 31;
        const float* Ai = A + i * 64;
        const float* Aj = A + j * 64;
        cw[lane]      = Ai[lane] * Aj[lane];
        cw[lane + 32] = Ai[lane + 32] * Aj[lane + 32];
        __syncwarp();

        float acc0 = ROW[i * 64 + lane]      + COL[j * 64 + lane]      + R[lane];
        float acc1 = ROW[i * 64 + lane + 32] + COL[j * 64 + lane + 32] + R[lane + 32];
        const float4* c4 = (const float4*)cw;
#pragma unroll
        for (int q = 0; q < 16; q++) {
            float4 c = c4[q];
            float4 u = wk0[q];
            float4 v = wk1[q];
            acc0 = fmaf(c.x, u.x, acc0); acc0 = fmaf(c.y, u.y, acc0);
            acc0 = fmaf(c.z, u.z, acc0); acc0 = fmaf(c.w, u.w, acc0);
            acc1 = fmaf(c.x, v.x, acc1); acc1 = fmaf(c.y, v.y, acc1);
            acc1 = fmaf(c.z, v.z, acc1); acc1 = fmaf(c.w, v.w, acc1);
        }
        sum0 += fmaxf(acc0, 0.f);
        sum1 += fmaxf(acc1, 0.f);
        __syncwarp();
    }

    // block reduce (deterministic, no atomics)
    cw[lane]      = sum0;
    cw[lane + 32] = sum1;
    __syncthreads();
    if (tid < 64) {
        float t = 0.f;
#pragma unroll
        for (int w = 0; w < 8; w++) t += C[w * 64 + tid];
        g_part[blockIdx.x * 64 + tid] = t;
    }
}

// ---------------- kernel 5: reduce over k, relu, final linear -----------------
__global__ void __launch_bounds__(512) k_out(const float* __restrict__ out_w,
                                             const float* __restrict__ out_b,
                                             float* __restrict__ out) {
    int tid = threadIdx.x;
    int bb = tid >> 5;        // 16 batches = 16 warps
    int lane = tid & 31;
    float a0 = 0.f, a1 = 0.f;
    for (int k = 0; k < 32; k++) {
        const float* p = g_part + (bb * 32 + k) * 64;
        a0 += p[lane];
        a1 += p[lane + 32];
    }
    float x0 = fmaxf(a0 * (1.f / 32768.f), 0.f);
    float x1 = fmaxf(a1 * (1.f / 32768.f), 0.f);
    float acc = x0 * out_w[lane] + x1 * out_w[lane + 32];
#pragma unroll
    for (int off = 16; off; off >>= 1)
        acc += __shfl_down_sync(0xffffffffu, acc, off);
    if (lane == 0) out[bb] = acc + out_b[0];
}

// ---------------- launch ------------------------------------------------------
extern "C" void kernel_launch(void* const* d_in, const int* in_sizes, int n_in,
                              void* d_out, int out_size) {
    const float* x       = (const float*)d_in[0];
    const float* conv1_w = (const float*)d_in[1];
    const float* conv1_b = (const float*)d_in[2];
    const float* conv2_w = (const float*)d_in[3];
    const float* conv2_b = (const float*)d_in[4];
    const float* fc_w    = (const float*)d_in[5];
    const float* fc_b    = (const float*)d_in[6];
    const float* eq_w    = (const float*)d_in[7];
    const float* eq_b    = (const float*)d_in[8];
    const float* out_w   = (const float*)d_in[9];
    const float* out_b   = (const float*)d_in[10];
    float* out = (float*)d_out;

    static bool attr_done = false;
    // (idempotent; cheap to repeat — avoid static guard semantics issues by
    //  simply calling every time)
    (void)attr_done;
    cudaFuncSetAttribute(k_conv2, cudaFuncAttributeMaxDynamicSharedMemorySize, 99328);
    cudaFuncSetAttribute(k_fc,    cudaFuncAttributeMaxDynamicSharedMemorySize, 100352);
    cudaFuncSetAttribute(k_eq,    cudaFuncAttributeMaxDynamicSharedMemorySize, 60928);

    k_prep<<<16, 256>>>(eq_w);
    k_conv1<<<NIMG, 256>>>(x, conv1_w, conv1_b);
    k_conv2<<<NIMG, 256, 99328>>>(conv2_w, conv2_b);
    k_fc<<<NIMG / 8, 256, 100352>>>(fc_w, fc_b);
    k_eq<<<NIMG, 256, 60928>>>(eq_b);
    k_out<<<1, 512>>>(out_w, out_b, out);
}

// round 2
// speedup vs baseline: 1.8907x; 1.8907x over previous
#include <cuda_runtime.h>
#include <cuda_bf16.h>

// B=16, K=32, H=W=28, HID=OUT=64, NOPS=8, N = B*K = 512 images
#define NIMG 512

// ---------------- scratch -----------------------------------------------------
__device__ float g_h1p[NIMG * 32 * 14 * 14];   // conv1+relu+pool out
__device__ float g_h2p[NIMG * 64 * 7 * 7];     // conv2+relu+pool out
__device__ float g_feat[NIMG * 64];            // fc+relu out
__device__ float g_wt[8 * 64 * 64];            // eq_w transposed: [o][d*64+e]
__device__ float g_part[NIMG * 64];            // per-(b,k) partial relu-sums
__device__ float g_fcpart[8 * NIMG * 64];      // fc k-split partials

// ---------------- kernel 0: transpose eq_w ------------------------------------
__global__ void k_prep(const float* __restrict__ eq_w) {
    int gid = blockIdx.x * blockDim.x + threadIdx.x;
    int nth = gridDim.x * blockDim.x;
    for (int idx = gid; idx < 8 * 64 * 64; idx += nth) {
        int o = idx & 7;
        int de = idx >> 3;                       // d*64 + e
        g_wt[o * 4096 + de] = eq_w[idx];
    }
}

// ---------------- kernel 1: conv1(1->32) + relu + maxpool2 --------------------
// thread = pooled pixel (196 active of 256); all 32 co inner (broadcast weights)
__global__ void __launch_bounds__(256) k_conv1(const float* __restrict__ x,
                                               const float* __restrict__ w,
                                               const float* __restrict__ bias) {
    __shared__ float smin[784];
    __shared__ float smw[288];
    __shared__ float smb[32];
    int n = blockIdx.x;
    int tid = threadIdx.x;
    for (int idx = tid; idx < 784; idx += 256) smin[idx] = x[n * 784 + idx];
    for (int idx = tid; idx < 288; idx += 256) smw[idx] = w[idx];
    if (tid < 32) smb[tid] = bias[tid];
    __syncthreads();

    if (tid < 196) {
        int oy = tid / 14, ox = tid % 14;
        float patch[4][4];
#pragma unroll
        for (int r = 0; r < 4; r++) {
            int y = oy * 2 - 1 + r;
#pragma unroll
            for (int cc = 0; cc < 4; cc++) {
                int xx = ox * 2 - 1 + cc;
                patch[r][cc] = (y >= 0 && y < 28 && xx >= 0 && xx < 28)
                                   ? smin[y * 28 + xx] : 0.f;
            }
        }
#pragma unroll 4
        for (int co = 0; co < 32; co++) {
            float b0 = smb[co];
            float s00 = b0, s01 = b0, s10 = b0, s11 = b0;
            const float* wp = smw + co * 9;
#pragma unroll
            for (int ky = 0; ky < 3; ky++)
#pragma unroll
                for (int kx = 0; kx < 3; kx++) {
                    float wv = wp[ky * 3 + kx];
                    s00 = fmaf(patch[ky][kx],     wv, s00);
                    s01 = fmaf(patch[ky][kx + 1], wv, s01);
                    s10 = fmaf(patch[ky + 1][kx],     wv, s10);
                    s11 = fmaf(patch[ky + 1][kx + 1], wv, s11);
                }
            float m = fmaxf(fmaxf(s00, s01), fmaxf(s10, s11));
            g_h1p[n * 6272 + co * 196 + tid] = fmaxf(m, 0.f);
        }
    }
}

// ---------------- kernel 2: conv2(32->64) + relu + maxpool2 -------------------
// 512 threads: thread = (co_group of 8, pooled pixel). Patch amortized over
// 8 output channels -> FMA-bound. dyn smem = 99072 B.
__global__ void __launch_bounds__(512) k_conv2(const float* __restrict__ w,
                                               const float* __restrict__ bias) {
    extern __shared__ float sm[];
    float* smin = sm;              // 6272
    float* smw  = sm + 6272;       // 18432
    float* smb  = sm + 24704;      // 64
    int n = blockIdx.x;
    int tid = threadIdx.x;
    for (int idx = tid; idx < 6272; idx += 512) smin[idx] = g_h1p[n * 6272 + idx];
    for (int idx = tid; idx < 18432; idx += 512) smw[idx] = w[idx];
    if (tid < 64) smb[tid] = bias[tid];
    __syncthreads();

    int cog = tid >> 6;            // 0..7 -> co = cog*8 + c
    int pslot = tid & 63;
    if (pslot < 49) {
        int oy = pslot / 7, ox = pslot % 7;
        float acc[8][4];
#pragma unroll
        for (int c = 0; c < 8; c++) {
            float b0 = smb[cog * 8 + c];
            acc[c][0] = b0; acc[c][1] = b0; acc[c][2] = b0; acc[c][3] = b0;
        }
        for (int ci = 0; ci < 32; ci++) {
            const float* ip = smin + ci * 196;
            float patch[4][4];
#pragma unroll
            for (int r = 0; r < 4; r++) {
                int y = oy * 2 - 1 + r;
#pragma unroll
                for (int cc = 0; cc < 4; cc++) {
                    int xx = ox * 2 - 1 + cc;
                    patch[r][cc] = (y >= 0 && y < 14 && xx >= 0 && xx < 14)
                                       ? ip[y * 14 + xx] : 0.f;
                }
            }
#pragma unroll
            for (int c = 0; c < 8; c++) {
                const float* wp = smw + ((cog * 8 + c) * 32 + ci) * 9;
#pragma unroll
                for (int ky = 0; ky < 3; ky++)
#pragma unroll
                    for (int kx = 0; kx < 3; kx++) {
                        float wv = wp[ky * 3 + kx];
                        acc[c][0] = fmaf(patch[ky][kx],     wv, acc[c][0]);
                        acc[c][1] = fmaf(patch[ky][kx + 1], wv, acc[c][1]);
                        acc[c][2] = fmaf(patch[ky + 1][kx],     wv, acc[c][2]);
                        acc[c][3] = fmaf(patch[ky + 1][kx + 1], wv, acc[c][3]);
                    }
            }
        }
#pragma unroll
        for (int c = 0; c < 8; c++) {
            float m = fmaxf(fmaxf(acc[c][0], acc[c][1]), fmaxf(acc[c][2], acc[c][3]));
            g_h2p[n * 3136 + (cog * 8 + c) * 49 + pslot] = fmaxf(m, 0.f);
        }
    }
}

// ---------------- kernel 3: fc GEMM, k-split partials --------------------------
// grid 256 = 32 image-tiles(16 imgs) x 8 k-splits(392). dyn smem 16*393 floats.
__global__ void __launch_bounds__(256) k_fc(const float* __restrict__ fcw) {
    extern __shared__ float As[];  // [16][393]
    int it = blockIdx.x >> 3, ks = blockIdx.x & 7;
    int n0 = it * 16, kbase = ks * 392;
    int tid = threadIdx.x;
    for (int idx = tid; idx < 16 * 392; idx += 256) {
        int im = idx / 392, kk = idx - im * 392;
        As[im * 393 + kk] = g_h2p[(n0 + im) * 3136 + kbase + kk];
    }
    __syncthreads();

    int h = tid >> 2, ig = tid & 3;
    const float* wrow = fcw + h * 3136 + kbase;
    float acc[4] = {0.f, 0.f, 0.f, 0.f};
#pragma unroll 4
    for (int kk = 0; kk < 392; kk++) {
        float wv = __ldg(wrow + kk);
#pragma unroll
        for (int m = 0; m < 4; m++)
            acc[m] = fmaf(wv, As[(ig * 4 + m) * 393 + kk], acc[m]);
    }
#pragma unroll
    for (int m = 0; m < 4; m++)
        g_fcpart[ks * 32768 + (n0 + ig * 4 + m) * 64 + h] = acc[m];
}

// ---------------- kernel 3b: reduce k-splits + bias + relu --------------------
__global__ void __launch_bounds__(512) k_fcred(const float* __restrict__ fcb) {
    int idx = blockIdx.x * 512 + threadIdx.x;   // grid 64 -> 32768
    float s = 0.f;
#pragma unroll
    for (int r = 0; r < 8; r++) s += g_fcpart[r * 32768 + idx];
    g_feat[idx] = fmaxf(s + fcb[idx & 63], 0.f);
}

// ---------------- kernel 4: equivariant block ---------------------------------
// One block per (b,k). Per row i: WKi[d,e] = A[i,d]*WK[d,e] (smem, double-buf),
// then x6[j,e] = sum_d A[j,d]*WKi[d,e] + ROW[i,e] + COL[j,e] + R[e];
// relu-summed per e. lane = j, warp owns 8 e channels.
__global__ void __launch_bounds__(256) k_eq(const float* __restrict__ eq_b) {
    extern __shared__ float sm[];
    float* At   = sm;            // 64*33 = 2112 : At[d*33+i]
    float* WKde = sm + 2112;     // 4096 : [d*64+e]
    float* WKi0 = sm + 6208;     // 4096 (also T during prologue)
    float* WKi1 = sm + 10304;    // 4096
    float* ROWs = sm + 14400;    // 2048 : [i*64+e]
    float* COLt = sm + 16448;    // 2048 : [e*32+j]
    float* S    = sm + 18496;    // 64
    float* R    = sm + 18560;    // 64
    // total 18624 floats = 74496 B

    int b = blockIdx.x >> 5;
    int k = blockIdx.x & 31;
    int tid = threadIdx.x, warp = tid >> 5, lane = tid & 31;

    const float* W0 = g_wt;
    const float* W1 = g_wt + 1 * 4096;
    const float* W2 = g_wt + 2 * 4096;
    const float* W3 = g_wt + 3 * 4096;
    const float* W4 = g_wt + 4 * 4096;
    const float* W5 = g_wt + 5 * 4096;
    const float* W6 = g_wt + 6 * 4096;
    const float* W7 = g_wt + 7 * 4096;

    for (int idx = tid; idx < 2048; idx += 256) {
        int i = idx >> 6, d = idx & 63;
        At[d * 33 + i] = g_feat[b * 2048 + idx];
    }
    __syncthreads();
    if (tid < 64) {
        float a = 0.f;
#pragma unroll
        for (int i = 0; i < 32; i++) a += At[tid * 33 + i];
        S[tid] = a * (1.f / 32.f);
    }
    __syncthreads();

    float* T = WKi0;
    for (int idx = tid; idx < 4096; idx += 256) {
        int d = idx >> 6;
        float sd = S[d], a = At[d * 33 + k];
        WKde[idx] = fmaf(a, W0[idx], sd * W3[idx]);
        T[idx]    = sd * fmaf(a, W2[idx], sd * W6[idx]);
    }
    if (tid < 64) {
        float acc = 0.f;
        for (int d = 0; d < 64; d++) {
            float sd = S[d];
            acc += sd * sd * fmaf(At[d * 33 + k], W4[d * 64 + tid], sd * W7[d * 64 + tid]);
        }
        R[tid] = acc + eq_b[tid];
    }
    __syncthreads();

    // ROWs = A @ T_row
    for (int idx = tid; idx < 2048; idx += 256) {
        int i = idx >> 6, e = idx & 63;
        float acc = 0.f;
#pragma unroll 8
        for (int d = 0; d < 64; d++) acc = fmaf(At[d * 33 + i], T[d * 64 + e], acc);
        ROWs[idx] = acc;
    }
    __syncthreads();

    // T_col (overwrites WKi0)
    for (int idx = tid; idx < 4096; idx += 256) {
        int d = idx >> 6;
        float sd = S[d];
        T[idx] = sd * fmaf(At[d * 33 + k], W1[idx], sd * W5[idx]);
    }
    __syncthreads();

    // COLt[e*32+j] = sum_d A[j,d]*T[d,e]
    for (int idx = tid; idx < 2048; idx += 256) {
        int e = idx >> 5, j = idx & 31;
        float acc = 0.f;
#pragma unroll 8
        for (int d = 0; d < 64; d++) acc = fmaf(At[d * 33 + j], T[d * 64 + e], acc);
        COLt[idx] = acc;
    }
    __syncthreads();

    int e0 = warp * 8;
    float esum[8] = {0, 0, 0, 0, 0, 0, 0, 0};
    float cbase[8];
#pragma unroll
    for (int t = 0; t < 8; t++) cbase[t] = COLt[(e0 + t) * 32 + lane] + R[e0 + t];

    for (int i = 0; i < 32; i++) {
        float* WKi = (i & 1) ? WKi1 : WKi0;
        // build WKi[d,e] = A[i,d] * WK[d,e]
        for (int idx = tid; idx < 4096; idx += 256) {
            int d = idx >> 6;
            WKi[idx] = At[d * 33 + i] * WKde[idx];
        }
        __syncthreads();

        float acc[8];
        const float* rw = ROWs + i * 64 + e0;
#pragma unroll
        for (int t = 0; t < 8; t++) acc[t] = cbase[t] + rw[t];

#pragma unroll 8
        for (int d = 0; d < 64; d++) {
            float a = At[d * 33 + lane];
            float4 w0 = *(const float4*)(WKi + d * 64 + e0);
            float4 w1 = *(const float4*)(WKi + d * 64 + e0 + 4);
            acc[0] = fmaf(a, w0.x, acc[0]); acc[1] = fmaf(a, w0.y, acc[1]);
            acc[2] = fmaf(a, w0.z, acc[2]); acc[3] = fmaf(a, w0.w, acc[3]);
            acc[4] = fmaf(a, w1.x, acc[4]); acc[5] = fmaf(a, w1.y, acc[5]);
            acc[6] = fmaf(a, w1.z, acc[6]); acc[7] = fmaf(a, w1.w, acc[7]);
        }
#pragma unroll
        for (int t = 0; t < 8; t++) esum[t] += fmaxf(acc[t], 0.f);
    }

#pragma unroll
    for (int t = 0; t < 8; t++) {
        float v = esum[t];
#pragma unroll
        for (int off = 16; off; off >>= 1)
            v += __shfl_down_sync(0xffffffffu, v, off);
        if (lane == 0) g_part[blockIdx.x * 64 + e0 + t] = v;
    }
}

// ---------------- kernel 5: reduce over k, relu, final linear -----------------
__global__ void __launch_bounds__(512) k_out(const float* __restrict__ out_w,
                                             const float* __restrict__ out_b,
                                             float* __restrict__ out) {
    int tid = threadIdx.x;
    int bb = tid >> 5;
    int lane = tid & 31;
    float a0 = 0.f, a1 = 0.f;
    for (int k = 0; k < 32; k++) {
        const float* p = g_part + (bb * 32 + k) * 64;
        a0 += p[lane];
        a1 += p[lane + 32];
    }
    float x0 = fmaxf(a0 * (1.f / 32768.f), 0.f);
    float x1 = fmaxf(a1 * (1.f / 32768.f), 0.f);
    float acc = x0 * out_w[lane] + x1 * out_w[lane + 32];
#pragma unroll
    for (int off = 16; off; off >>= 1)
        acc += __shfl_down_sync(0xffffffffu, acc, off);
    if (lane == 0) out[bb] = acc + out_b[0];
}

// ---------------- launch ------------------------------------------------------
extern "C" void kernel_launch(void* const* d_in, const int* in_sizes, int n_in,
                              void* d_out, int out_size) {
    const float* x       = (const float*)d_in[0];
    const float* conv1_w = (const float*)d_in[1];
    const float* conv1_b = (const float*)d_in[2];
    const float* conv2_w = (const float*)d_in[3];
    const float* conv2_b = (const float*)d_in[4];
    const float* fc_w    = (const float*)d_in[5];
    const float* fc_b    = (const float*)d_in[6];
    const float* eq_w    = (const float*)d_in[7];
    const float* eq_b    = (const float*)d_in[8];
    const float* out_w   = (const float*)d_in[9];
    const float* out_b   = (const float*)d_in[10];
    float* out = (float*)d_out;

    cudaFuncSetAttribute(k_conv2, cudaFuncAttributeMaxDynamicSharedMemorySize, 99072);
    cudaFuncSetAttribute(k_fc,    cudaFuncAttributeMaxDynamicSharedMemorySize, 25152);
    cudaFuncSetAttribute(k_eq,    cudaFuncAttributeMaxDynamicSharedMemorySize, 74496);

    k_prep<<<16, 256>>>(eq_w);
    k_conv1<<<NIMG, 256>>>(x, conv1_w, conv1_b);
    k_conv2<<<NIMG, 512, 99072>>>(conv2_w, conv2_b);
    k_fc<<<256, 256, 25152>>>(fc_w);
    k_fcred<<<64, 512>>>(fc_b);
    k_eq<<<NIMG, 256, 74496>>>(eq_b);
    k_out<<<1, 512>>>(out_w, out_b, out);
}

// round 3
// speedup vs baseline: 2.3680x; 1.2524x over previous
#include <cuda_runtime.h>
#include <cuda_bf16.h>

// B=16, K=32, H=W=28, HID=OUT=64, NOPS=8, N = B*K = 512 images
#define NIMG 512
#define FC_SPLIT 14
#define FC_SLICE 224     // 3136 / 14

// ---------------- scratch -----------------------------------------------------
__device__ float g_h1p[NIMG * 32 * 14 * 14];     // conv1+relu+pool out
__device__ float g_h2p[NIMG * 64 * 7 * 7];       // conv2+relu+pool out
__device__ float g_feat[NIMG * 64];              // fc+relu out
__device__ float g_wt[8 * 64 * 64];              // eq_w transposed: [o][d*64+e]
__device__ float g_part[NIMG * 64];              // per-(b,k) partial relu-sums
__device__ float g_fcpart[FC_SPLIT * NIMG * 64]; // fc k-split partials

// ---------------- kernel 0: transpose eq_w ------------------------------------
__global__ void k_prep(const float* __restrict__ eq_w) {
    int gid = blockIdx.x * blockDim.x + threadIdx.x;
    int nth = gridDim.x * blockDim.x;
    for (int idx = gid; idx < 8 * 64 * 64; idx += nth) {
        int o = idx & 7;
        int de = idx >> 3;                       // d*64 + e
        g_wt[o * 4096 + de] = eq_w[idx];
    }
}

// ---------------- kernel 1: conv1(1->32) + relu + maxpool2 --------------------
__global__ void __launch_bounds__(224) k_conv1(const float* __restrict__ x,
                                               const float* __restrict__ w,
                                               const float* __restrict__ bias) {
    __shared__ float smin[784];
    __shared__ float smw[288];
    __shared__ float smb[32];
    int n = blockIdx.x;
    int tid = threadIdx.x;
    for (int idx = tid; idx < 784; idx += 224) smin[idx] = x[n * 784 + idx];
    for (int idx = tid; idx < 288; idx += 224) smw[idx] = w[idx];
    if (tid < 32) smb[tid] = bias[tid];
    __syncthreads();

    if (tid < 196) {
        int oy = tid / 14, ox = tid % 14;
        float patch[4][4];
#pragma unroll
        for (int r = 0; r < 4; r++) {
            int y = oy * 2 - 1 + r;
#pragma unroll
            for (int cc = 0; cc < 4; cc++) {
                int xx = ox * 2 - 1 + cc;
                patch[r][cc] = (y >= 0 && y < 28 && xx >= 0 && xx < 28)
                                   ? smin[y * 28 + xx] : 0.f;
            }
        }
#pragma unroll 4
        for (int co = 0; co < 32; co++) {
            float b0 = smb[co];
            float s00 = b0, s01 = b0, s10 = b0, s11 = b0;
            const float* wp = smw + co * 9;
#pragma unroll
            for (int ky = 0; ky < 3; ky++)
#pragma unroll
                for (int kx = 0; kx < 3; kx++) {
                    float wv = wp[ky * 3 + kx];
                    s00 = fmaf(patch[ky][kx],     wv, s00);
                    s01 = fmaf(patch[ky][kx + 1], wv, s01);
                    s10 = fmaf(patch[ky + 1][kx],     wv, s10);
                    s11 = fmaf(patch[ky + 1][kx + 1], wv, s11);
                }
            float m = fmaxf(fmaxf(s00, s01), fmaxf(s10, s11));
            g_h1p[n * 6272 + co * 196 + tid] = fmaxf(m, 0.f);
        }
    }
}

// ---------------- kernel 2: conv2(32->64) + relu + maxpool2 -------------------
// 392 threads = 8 co-groups x 49 pooled pixels -> 100% active lanes.
__global__ void __launch_bounds__(392) k_conv2(const float* __restrict__ w,
                                               const float* __restrict__ bias) {
    extern __shared__ float sm[];
    float* smin = sm;              // 6272
    float* smw  = sm + 6272;       // 18432
    float* smb  = sm + 24704;      // 64
    int n = blockIdx.x;
    int tid = threadIdx.x;
    for (int idx = tid; idx < 6272; idx += 392) smin[idx] = g_h1p[n * 6272 + idx];
    for (int idx = tid; idx < 18432; idx += 392) smw[idx] = w[idx];
    if (tid < 64) smb[tid] = bias[tid];
    __syncthreads();

    int cog = tid / 49;            // 0..7 -> co = cog*8 + c
    int pslot = tid - cog * 49;    // 0..48
    int oy = pslot / 7, ox = pslot % 7;
    float acc[8][4];
#pragma unroll
    for (int c = 0; c < 8; c++) {
        float b0 = smb[cog * 8 + c];
        acc[c][0] = b0; acc[c][1] = b0; acc[c][2] = b0; acc[c][3] = b0;
    }
    for (int ci = 0; ci < 32; ci++) {
        const float* ip = smin + ci * 196;
        float patch[4][4];
#pragma unroll
        for (int r = 0; r < 4; r++) {
            int y = oy * 2 - 1 + r;
#pragma unroll
            for (int cc = 0; cc < 4; cc++) {
                int xx = ox * 2 - 1 + cc;
                patch[r][cc] = (y >= 0 && y < 14 && xx >= 0 && xx < 14)
                                   ? ip[y * 14 + xx] : 0.f;
            }
        }
#pragma unroll
        for (int c = 0; c < 8; c++) {
            const float* wp = smw + ((cog * 8 + c) * 32 + ci) * 9;
#pragma unroll
            for (int ky = 0; ky < 3; ky++)
#pragma unroll
                for (int kx = 0; kx < 3; kx++) {
                    float wv = wp[ky * 3 + kx];
                    acc[c][0] = fmaf(patch[ky][kx],     wv, acc[c][0]);
                    acc[c][1] = fmaf(patch[ky][kx + 1], wv, acc[c][1]);
                    acc[c][2] = fmaf(patch[ky + 1][kx],     wv, acc[c][2]);
                    acc[c][3] = fmaf(patch[ky + 1][kx + 1], wv, acc[c][3]);
                }
        }
    }
#pragma unroll
    for (int c = 0; c < 8; c++) {
        float m = fmaxf(fmaxf(acc[c][0], acc[c][1]), fmaxf(acc[c][2], acc[c][3]));
        g_h2p[n * 3136 + (cog * 8 + c) * 49 + pslot] = fmaxf(m, 0.f);
    }
}

// ---------------- kernel 3: fc GEMM (tiled, register-blocked) ------------------
// grid = 8 M-tiles x 14 K-splits = 112 blocks. Block: 64 imgs x 64 h, 256 thr,
// 4x4 per thread, k-chunks of 16.
__global__ void __launch_bounds__(256) k_fc(const float* __restrict__ fcw) {
    __shared__ float As[16][68];
    __shared__ float Bs[16][68];
    int mt = blockIdx.x / FC_SPLIT, ks = blockIdx.x - mt * FC_SPLIT;
    int n0 = mt * 64, kbase = ks * FC_SLICE;
    int tid = threadIdx.x;
    int ty = tid >> 4, tx = tid & 15;
    int lrow = tid >> 2;          // 0..63
    int lkq  = tid & 3;           // kk quad

    float acc[4][4] = {};
    for (int kb = 0; kb < FC_SLICE; kb += 16) {
        float4 a4 = *(const float4*)&g_h2p[(n0 + lrow) * 3136 + kbase + kb + lkq * 4];
        float4 b4 = *(const float4*)&fcw[lrow * 3136 + kbase + kb + lkq * 4];
        __syncthreads();
        As[lkq * 4 + 0][lrow] = a4.x; As[lkq * 4 + 1][lrow] = a4.y;
        As[lkq * 4 + 2][lrow] = a4.z; As[lkq * 4 + 3][lrow] = a4.w;
        Bs[lkq * 4 + 0][lrow] = b4.x; Bs[lkq * 4 + 1][lrow] = b4.y;
        Bs[lkq * 4 + 2][lrow] = b4.z; Bs[lkq * 4 + 3][lrow] = b4.w;
        __syncthreads();
#pragma unroll
        for (int kk = 0; kk < 16; kk++) {
            float4 av = *(const float4*)&As[kk][ty * 4];
            float4 bv = *(const float4*)&Bs[kk][tx * 4];
            float a[4] = {av.x, av.y, av.z, av.w};
            float bb[4] = {bv.x, bv.y, bv.z, bv.w};
#pragma unroll
            for (int m = 0; m < 4; m++)
#pragma unroll
                for (int nn = 0; nn < 4; nn++)
                    acc[m][nn] = fmaf(a[m], bb[nn], acc[m][nn]);
        }
    }
    float* outp = g_fcpart + ks * (NIMG * 64);
#pragma unroll
    for (int m = 0; m < 4; m++)
#pragma unroll
        for (int nn = 0; nn < 4; nn++)
            outp[(n0 + ty * 4 + m) * 64 + tx * 4 + nn] = acc[m][nn];
}

// ---------------- kernel 3b: reduce k-splits + bias + relu --------------------
__global__ void __launch_bounds__(512) k_fcred(const float* __restrict__ fcb) {
    int idx = blockIdx.x * 512 + threadIdx.x;   // grid 64 -> 32768
    float s = 0.f;
#pragma unroll
    for (int r = 0; r < FC_SPLIT; r++) s += g_fcpart[r * (NIMG * 64) + idx];
    g_feat[idx] = fmaxf(s + fcb[idx & 63], 0.f);
}

// ---------------- kernel 4: equivariant block ---------------------------------
// One block per (b,k). x6[i,j,e] = sum_d a_i[d] a_j[d] WK[d,e] + ROW[i,e]
// + COL[j,e] + R[e]; relu-summed over (i,j). lane = j; warp owns 8 e; i in pairs.
__global__ void __launch_bounds__(256, 2) k_eq(const float* __restrict__ eq_b) {
    extern __shared__ float sm[];
    float* At   = sm;            // 64*33 = 2112 : At[d*33 + i]
    float* WK   = sm + 2112;     // 4096 : [d*64+e]  (temp T during prologue)
    float* ROWs = sm + 6208;     // 2048 : [i*64+e]
    float* COLt = sm + 8256;     // 2048 : [e*32+j]
    float* S    = sm + 10304;    // 64
    float* R    = sm + 10368;    // 64
    // total 10432 floats = 41728 B

    int b = blockIdx.x >> 5;
    int k = blockIdx.x & 31;
    int tid = threadIdx.x, warp = tid >> 5, lane = tid & 31;

    const float* W0 = g_wt;
    const float* W1 = g_wt + 1 * 4096;
    const float* W2 = g_wt + 2 * 4096;
    const float* W3 = g_wt + 3 * 4096;
    const float* W4 = g_wt + 4 * 4096;
    const float* W5 = g_wt + 5 * 4096;
    const float* W6 = g_wt + 6 * 4096;
    const float* W7 = g_wt + 7 * 4096;

    for (int idx = tid; idx < 2048; idx += 256) {
        int i = idx >> 6, d = idx & 63;
        At[d * 33 + i] = g_feat[b * 2048 + idx];
    }
    __syncthreads();
    if (tid < 64) {
        float a = 0.f;
#pragma unroll
        for (int i = 0; i < 32; i++) a += At[tid * 33 + i];
        S[tid] = a * (1.f / 32.f);
    }
    __syncthreads();

    float* T = WK;   // reuse as temp
    for (int idx = tid; idx < 4096; idx += 256) {
        int d = idx >> 6;
        float sd = S[d];
        T[idx] = sd * fmaf(At[d * 33 + k], W2[idx], sd * W6[idx]);
    }
    if (tid < 64) {
        float acc = 0.f;
        for (int d = 0; d < 64; d++) {
            float sd = S[d];
            acc += sd * sd * fmaf(At[d * 33 + k], W4[d * 64 + tid], sd * W7[d * 64 + tid]);
        }
        R[tid] = acc + eq_b[tid];
    }
    __syncthreads();

    // ROWs = A @ T_row
    for (int idx = tid; idx < 2048; idx += 256) {
        int i = idx >> 6, e = idx & 63;
        float acc = 0.f;
#pragma unroll 8
        for (int d = 0; d < 64; d++) acc = fmaf(At[d * 33 + i], T[d * 64 + e], acc);
        ROWs[idx] = acc;
    }
    __syncthreads();

    // T = col temp
    for (int idx = tid; idx < 4096; idx += 256) {
        int d = idx >> 6;
        float sd = S[d];
        T[idx] = sd * fmaf(At[d * 33 + k], W1[idx], sd * W5[idx]);
    }
    __syncthreads();

    // COLt[e*32+j]
    for (int idx = tid; idx < 2048; idx += 256) {
        int e = idx >> 5, j = idx & 31;
        float acc = 0.f;
#pragma unroll 8
        for (int d = 0; d < 64; d++) acc = fmaf(At[d * 33 + j], T[d * 64 + e], acc);
        COLt[idx] = acc;
    }
    __syncthreads();

    // final WK[d,e] = a_k[d]*W0 + s[d]*W3
    for (int idx = tid; idx < 4096; idx += 256) {
        int d = idx >> 6;
        WK[idx] = fmaf(At[d * 33 + k], W0[idx], S[d] * W3[idx]);
    }
    __syncthreads();

    int e0 = warp * 8;
    float esum[8] = {0, 0, 0, 0, 0, 0, 0, 0};
    float cbase[8];
#pragma unroll
    for (int t = 0; t < 8; t++) cbase[t] = COLt[(e0 + t) * 32 + lane] + R[e0 + t];

    for (int ip = 0; ip < 16; ip++) {
        int i0 = ip * 2, i1 = ip * 2 + 1;
        float acc0[8], acc1[8];
        float4 r0a = *(const float4*)(ROWs + i0 * 64 + e0);
        float4 r0b = *(const float4*)(ROWs + i0 * 64 + e0 + 4);
        float4 r1a = *(const float4*)(ROWs + i1 * 64 + e0);
        float4 r1b = *(const float4*)(ROWs + i1 * 64 + e0 + 4);
        acc0[0] = cbase[0] + r0a.x; acc0[1] = cbase[1] + r0a.y;
        acc0[2] = cbase[2] + r0a.z; acc0[3] = cbase[3] + r0a.w;
        acc0[4] = cbase[4] + r0b.x; acc0[5] = cbase[5] + r0b.y;
        acc0[6] = cbase[6] + r0b.z; acc0[7] = cbase[7] + r0b.w;
        acc1[0] = cbase[0] + r1a.x; acc1[1] = cbase[1] + r1a.y;
        acc1[2] = cbase[2] + r1a.z; acc1[3] = cbase[3] + r1a.w;
        acc1[4] = cbase[4] + r1b.x; acc1[5] = cbase[5] + r1b.y;
        acc1[6] = cbase[6] + r1b.z; acc1[7] = cbase[7] + r1b.w;

#pragma unroll 8
        for (int d = 0; d < 64; d++) {
            float aj = At[d * 33 + lane];
            float c0 = At[d * 33 + i0] * aj;
            float c1 = At[d * 33 + i1] * aj;
            float4 w0 = *(const float4*)(WK + d * 64 + e0);
            float4 w1 = *(const float4*)(WK + d * 64 + e0 + 4);
            acc0[0] = fmaf(c0, w0.x, acc0[0]); acc1[0] = fmaf(c1, w0.x, acc1[0]);
            acc0[1] = fmaf(c0, w0.y, acc0[1]); acc1[1] = fmaf(c1, w0.y, acc1[1]);
            acc0[2] = fmaf(c0, w0.z, acc0[2]); acc1[2] = fmaf(c1, w0.z, acc1[2]);
            acc0[3] = fmaf(c0, w0.w, acc0[3]); acc1[3] = fmaf(c1, w0.w, acc1[3]);
            acc0[4] = fmaf(c0, w1.x, acc0[4]); acc1[4] = fmaf(c1, w1.x, acc1[4]);
            acc0[5] = fmaf(c0, w1.y, acc0[5]); acc1[5] = fmaf(c1, w1.y, acc1[5]);
            acc0[6] = fmaf(c0, w1.z, acc0[6]); acc1[6] = fmaf(c1, w1.z, acc1[6]);
            acc0[7] = fmaf(c0, w1.w, acc0[7]); acc1[7] = fmaf(c1, w1.w, acc1[7]);
        }
#pragma unroll
        for (int t = 0; t < 8; t++)
            esum[t] += fmaxf(acc0[t], 0.f) + fmaxf(acc1[t], 0.f);
    }

#pragma unroll
    for (int t = 0; t < 8; t++) {
        float v = esum[t];
#pragma unroll
        for (int off = 16; off; off >>= 1)
            v += __shfl_down_sync(0xffffffffu, v, off);
        if (lane == 0) g_part[blockIdx.x * 64 + e0 + t] = v;
    }
}

// ---------------- kernel 5: reduce over k, relu, final linear -----------------
__global__ void __launch_bounds__(512) k_out(const float* __restrict__ out_w,
                                             const float* __restrict__ out_b,
                                             float* __restrict__ out) {
    int tid = threadIdx.x;
    int bb = tid >> 5;
    int lane = tid & 31;
    float a0 = 0.f, a1 = 0.f;
    for (int k = 0; k < 32; k++) {
        const float* p = g_part + (bb * 32 + k) * 64;
        a0 += p[lane];
        a1 += p[lane + 32];
    }
    float x0 = fmaxf(a0 * (1.f / 32768.f), 0.f);
    float x1 = fmaxf(a1 * (1.f / 32768.f), 0.f);
    float acc = x0 * out_w[lane] + x1 * out_w[lane + 32];
#pragma unroll
    for (int off = 16; off; off >>= 1)
        acc += __shfl_down_sync(0xffffffffu, acc, off);
    if (lane == 0) out[bb] = acc + out_b[0];
}

// ---------------- launch ------------------------------------------------------
extern "C" void kernel_launch(void* const* d_in, const int* in_sizes, int n_in,
                              void* d_out, int out_size) {
    const float* x       = (const float*)d_in[0];
    const float* conv1_w = (const float*)d_in[1];
    const float* conv1_b = (const float*)d_in[2];
    const float* conv2_w = (const float*)d_in[3];
    const float* conv2_b = (const float*)d_in[4];
    const float* fc_w    = (const float*)d_in[5];
    const float* fc_b    = (const float*)d_in[6];
    const float* eq_w    = (const float*)d_in[7];
    const float* eq_b    = (const float*)d_in[8];
    const float* out_w   = (const float*)d_in[9];
    const float* out_b   = (const float*)d_in[10];
    float* out = (float*)d_out;

    cudaFuncSetAttribute(k_conv2, cudaFuncAttributeMaxDynamicSharedMemorySize, 99072);
    cudaFuncSetAttribute(k_eq,    cudaFuncAttributeMaxDynamicSharedMemorySize, 41728);

    k_prep<<<16, 256>>>(eq_w);
    k_conv1<<<NIMG, 224>>>(x, conv1_w, conv1_b);
    k_conv2<<<NIMG, 392, 99072>>>(conv2_w, conv2_b);
    k_fc<<<8 * FC_SPLIT, 256>>>(fc_w);
    k_fcred<<<64, 512>>>(fc_b);
    k_eq<<<NIMG, 256, 41728>>>(eq_b);
    k_out<<<1, 512>>>(out_w, out_b, out);
}

// round 4
// speedup vs baseline: 2.5949x; 1.0958x over previous
#include <cuda_runtime.h>
#include <cuda_bf16.h>

// B=16, K=32, H=W=28, HID=OUT=64, NOPS=8, N = B*K = 512 images
#define NIMG 512
#define FC_SPLIT 28
#define FC_SLICE 112     // 3136 / 28

typedef unsigned long long ull;

// ---------------- packed fp32x2 helpers (Blackwell f32x2 pipe) -----------------
__device__ __forceinline__ ull pk2(float lo, float hi) {
    ull d;
    asm("mov.b64 %0, {%1, %2};" : "=l"(d)
        : "r"(__float_as_uint(lo)), "r"(__float_as_uint(hi)));
    return d;
}
__device__ __forceinline__ float2 upk2(ull v) {
    unsigned int lo, hi;
    asm("mov.b64 {%0, %1}, %2;" : "=r"(lo), "=r"(hi) : "l"(v));
    float2 f; f.x = __uint_as_float(lo); f.y = __uint_as_float(hi);
    return f;
}
__device__ __forceinline__ ull f2fma(ull a, ull b, ull c) {
    ull d;
    asm("fma.rn.f32x2 %0, %1, %2, %3;" : "=l"(d) : "l"(a), "l"(b), "l"(c));
    return d;
}
__device__ __forceinline__ ull f2mul(ull a, ull b) {
    ull d;
    asm("mul.rn.f32x2 %0, %1, %2;" : "=l"(d) : "l"(a), "l"(b));
    return d;
}

// ---------------- scratch -----------------------------------------------------
__device__ float g_h1p[NIMG * 32 * 14 * 14];     // conv1+relu+pool out
__device__ float g_h2p[NIMG * 64 * 7 * 7];       // conv2+relu+pool out
__device__ float g_feat[NIMG * 64];              // fc+relu out
__device__ float g_wt[8 * 64 * 64];              // eq_w transposed: [o][d*64+e]
__device__ float g_part[NIMG * 64];              // per-(b,k) partial relu-sums
__device__ float g_fcpart[FC_SPLIT * NIMG * 64]; // fc k-split partials

// ---------------- kernel 0: transpose eq_w ------------------------------------
__global__ void k_prep(const float* __restrict__ eq_w) {
    int gid = blockIdx.x * blockDim.x + threadIdx.x;
    int nth = gridDim.x * blockDim.x;
    for (int idx = gid; idx < 8 * 64 * 64; idx += nth) {
        int o = idx & 7;
        int de = idx >> 3;                       // d*64 + e
        g_wt[o * 4096 + de] = eq_w[idx];
    }
}

// ---------------- kernel 1: conv1(1->32) + relu + maxpool2 --------------------
__global__ void __launch_bounds__(224) k_conv1(const float* __restrict__ x,
                                               const float* __restrict__ w,
                                               const float* __restrict__ bias) {
    __shared__ float smin[784];
    __shared__ float smw[288];
    __shared__ float smb[32];
    int n = blockIdx.x;
    int tid = threadIdx.x;
    for (int idx = tid; idx < 784; idx += 224) smin[idx] = x[n * 784 + idx];
    for (int idx = tid; idx < 288; idx += 224) smw[idx] = w[idx];
    if (tid < 32) smb[tid] = bias[tid];
    __syncthreads();

    if (tid < 196) {
        int oy = tid / 14, ox = tid % 14;
        float patch[4][4];
#pragma unroll
        for (int r = 0; r < 4; r++) {
            int y = oy * 2 - 1 + r;
#pragma unroll
            for (int cc = 0; cc < 4; cc++) {
                int xx = ox * 2 - 1 + cc;
                patch[r][cc] = (y >= 0 && y < 28 && xx >= 0 && xx < 28)
                                   ? smin[y * 28 + xx] : 0.f;
            }
        }
        // packed overlapping pairs: pp[r][k] = {patch[r][k], patch[r][k+1]}
        ull pp[4][3];
#pragma unroll
        for (int r = 0; r < 4; r++)
#pragma unroll
            for (int kx = 0; kx < 3; kx++)
                pp[r][kx] = pk2(patch[r][kx], patch[r][kx + 1]);

#pragma unroll 4
        for (int co = 0; co < 32; co++) {
            float b0 = smb[co];
            ull accT = pk2(b0, b0);   // {s00, s01}
            ull accB = pk2(b0, b0);   // {s10, s11}
            const float* wp = smw + co * 9;
#pragma unroll
            for (int ky = 0; ky < 3; ky++)
#pragma unroll
                for (int kx = 0; kx < 3; kx++) {
                    float wv = wp[ky * 3 + kx];
                    ull w2 = pk2(wv, wv);
                    accT = f2fma(pp[ky][kx],     w2, accT);
                    accB = f2fma(pp[ky + 1][kx], w2, accB);
                }
            float2 t = upk2(accT), bt = upk2(accB);
            float m = fmaxf(fmaxf(t.x, t.y), fmaxf(bt.x, bt.y));
            g_h1p[n * 6272 + co * 196 + tid] = fmaxf(m, 0.f);
        }
    }
}

// ---------------- kernel 2: conv2(32->64) + relu + maxpool2 -------------------
// 392 threads = 8 co-groups x 49 pooled pixels; packed f32x2 accumulators.
__global__ void __launch_bounds__(392) k_conv2(const float* __restrict__ w,
                                               const float* __restrict__ bias) {
    extern __shared__ float sm[];
    float* smin = sm;              // 6272
    float* smw  = sm + 6272;       // 18432
    float* smb  = sm + 24704;      // 64
    int n = blockIdx.x;
    int tid = threadIdx.x;
    for (int idx = tid; idx < 6272; idx += 392) smin[idx] = g_h1p[n * 6272 + idx];
    for (int idx = tid; idx < 18432; idx += 392) smw[idx] = w[idx];
    if (tid < 64) smb[tid] = bias[tid];
    __syncthreads();

    int cog = tid / 49;            // 0..7 -> co = cog*8 + c
    int pslot = tid - cog * 49;    // 0..48
    int oy = pslot / 7, ox = pslot % 7;

    ull accT[8], accB[8];
#pragma unroll
    for (int c = 0; c < 8; c++) {
        float b0 = smb[cog * 8 + c];
        accT[c] = pk2(b0, b0);
        accB[c] = pk2(b0, b0);
    }

    for (int ci = 0; ci < 32; ci++) {
        const float* ip = smin + ci * 196;
        float patch[4][4];
#pragma unroll
        for (int r = 0; r < 4; r++) {
            int y = oy * 2 - 1 + r;
#pragma unroll
            for (int cc = 0; cc < 4; cc++) {
                int xx = ox * 2 - 1 + cc;
                patch[r][cc] = (y >= 0 && y < 14 && xx >= 0 && xx < 14)
                                   ? ip[y * 14 + xx] : 0.f;
            }
        }
        ull pp[4][3];
#pragma unroll
        for (int r = 0; r < 4; r++)
#pragma unroll
            for (int kx = 0; kx < 3; kx++)
                pp[r][kx] = pk2(patch[r][kx], patch[r][kx + 1]);

#pragma unroll
        for (int c = 0; c < 8; c++) {
            const float* wp = smw + ((cog * 8 + c) * 32 + ci) * 9;
#pragma unroll
            for (int ky = 0; ky < 3; ky++)
#pragma unroll
                for (int kx = 0; kx < 3; kx++) {
                    float wv = wp[ky * 3 + kx];
                    ull w2 = pk2(wv, wv);
                    accT[c] = f2fma(pp[ky][kx],     w2, accT[c]);
                    accB[c] = f2fma(pp[ky + 1][kx], w2, accB[c]);
                }
        }
    }
#pragma unroll
    for (int c = 0; c < 8; c++) {
        float2 t = upk2(accT[c]), bt = upk2(accB[c]);
        float m = fmaxf(fmaxf(t.x, t.y), fmaxf(bt.x, bt.y));
        g_h2p[n * 3136 + (cog * 8 + c) * 49 + pslot] = fmaxf(m, 0.f);
    }
}

// ---------------- kernel 3: fc GEMM (tiled, register-blocked) ------------------
// grid = 8 M-tiles x 28 K-splits = 224 blocks. Block: 64 imgs x 64 h, 256 thr,
// 4x4 per thread, k-chunks of 16.
__global__ void __launch_bounds__(256) k_fc(const float* __restrict__ fcw) {
    __shared__ float As[16][68];
    __shared__ float Bs[16][68];
    int mt = blockIdx.x / FC_SPLIT, ks = blockIdx.x - mt * FC_SPLIT;
    int n0 = mt * 64, kbase = ks * FC_SLICE;
    int tid = threadIdx.x;
    int ty = tid >> 4, tx = tid & 15;
    int lrow = tid >> 2;          // 0..63
    int lkq  = tid & 3;           // kk quad

    float acc[4][4] = {};
    for (int kb = 0; kb < FC_SLICE; kb += 16) {
        float4 a4 = *(const float4*)&g_h2p[(n0 + lrow) * 3136 + kbase + kb + lkq * 4];
        float4 b4 = *(const float4*)&fcw[lrow * 3136 + kbase + kb + lkq * 4];
        __syncthreads();
        As[lkq * 4 + 0][lrow] = a4.x; As[lkq * 4 + 1][lrow] = a4.y;
        As[lkq * 4 + 2][lrow] = a4.z; As[lkq * 4 + 3][lrow] = a4.w;
        Bs[lkq * 4 + 0][lrow] = b4.x; Bs[lkq * 4 + 1][lrow] = b4.y;
        Bs[lkq * 4 + 2][lrow] = b4.z; Bs[lkq * 4 + 3][lrow] = b4.w;
        __syncthreads();
#pragma unroll
        for (int kk = 0; kk < 16; kk++) {
            float4 av = *(const float4*)&As[kk][ty * 4];
            float4 bv = *(const float4*)&Bs[kk][tx * 4];
            float a[4] = {av.x, av.y, av.z, av.w};
            float bb[4] = {bv.x, bv.y, bv.z, bv.w};
#pragma unroll
            for (int m = 0; m < 4; m++)
#pragma unroll
                for (int nn = 0; nn < 4; nn++)
                    acc[m][nn] = fmaf(a[m], bb[nn], acc[m][nn]);
        }
    }
    float* outp = g_fcpart + ks * (NIMG * 64);
#pragma unroll
    for (int m = 0; m < 4; m++)
#pragma unroll
        for (int nn = 0; nn < 4; nn++)
            outp[(n0 + ty * 4 + m) * 64 + tx * 4 + nn] = acc[m][nn];
}

// ---------------- kernel 3b: reduce k-splits + bias + relu --------------------
__global__ void __launch_bounds__(512) k_fcred(const float* __restrict__ fcb) {
    int idx = blockIdx.x * 512 + threadIdx.x;   // grid 64 -> 32768
    float s = 0.f;
#pragma unroll
    for (int r = 0; r < FC_SPLIT; r++) s += g_fcpart[r * (NIMG * 64) + idx];
    g_feat[idx] = fmaxf(s + fcb[idx & 63], 0.f);
}

// ---------------- kernel 4: equivariant block (packed f32x2 main loop) --------
// One block per (b,k). x6[i,j,e] = sum_d a_i[d] a_j[d] WK[d,e] + ROW[i,e]
// + COL[j,e] + R[e]; relu-summed over (i,j). lane = j; warp owns 8 e (4 pairs);
// i processed 4 rows at a time.
__global__ void __launch_bounds__(256, 2) k_eq(const float* __restrict__ eq_b) {
    extern __shared__ float sm[];
    float* At   = sm;            // 64*36 = 2304 : At[d*36 + i]
    float* WK   = sm + 2304;     // 4096 : [d*64+e]  (temp T during prologue)
    float* ROWs = sm + 6400;     // 2048 : [i*64+e]
    float* COLt = sm + 8448;     // 2048 : [e*32+j]
    float* S    = sm + 10496;    // 64
    float* R    = sm + 10560;    // 64
    // total 10624 floats = 42496 B

    int b = blockIdx.x >> 5;
    int k = blockIdx.x & 31;
    int tid = threadIdx.x, warp = tid >> 5, lane = tid & 31;

    const float* W0 = g_wt;
    const float* W1 = g_wt + 1 * 4096;
    const float* W2 = g_wt + 2 * 4096;
    const float* W3 = g_wt + 3 * 4096;
    const float* W4 = g_wt + 4 * 4096;
    const float* W5 = g_wt + 5 * 4096;
    const float* W6 = g_wt + 6 * 4096;
    const float* W7 = g_wt + 7 * 4096;

    for (int idx = tid; idx < 2048; idx += 256) {
        int i = idx >> 6, d = idx & 63;
        At[d * 36 + i] = g_feat[b * 2048 + idx];
    }
    __syncthreads();
    if (tid < 64) {
        float a = 0.f;
#pragma unroll
        for (int i = 0; i < 32; i++) a += At[tid * 36 + i];
        S[tid] = a * (1.f / 32.f);
    }
    __syncthreads();

    float* T = WK;   // reuse as temp
    for (int idx = tid; idx < 4096; idx += 256) {
        int d = idx >> 6;
        float sd = S[d];
        T[idx] = sd * fmaf(At[d * 36 + k], W2[idx], sd * W6[idx]);
    }
    if (tid < 64) {
        float acc = 0.f;
        for (int d = 0; d < 64; d++) {
            float sd = S[d];
            acc += sd * sd * fmaf(At[d * 36 + k], W4[d * 64 + tid], sd * W7[d * 64 + tid]);
        }
        R[tid] = acc + eq_b[tid];
    }
    __syncthreads();

    // ROWs = A @ T_row  (packed over e-pairs)
    for (int idx = tid; idx < 1024; idx += 256) {
        int i = idx >> 5, ep = (idx & 31) * 2;
        ull acc = pk2(0.f, 0.f);
#pragma unroll 8
        for (int d = 0; d < 64; d++) {
            float a = At[d * 36 + i];
            acc = f2fma(pk2(a, a), *(const ull*)(T + d * 64 + ep), acc);
        }
        float2 r = upk2(acc);
        ROWs[i * 64 + ep] = r.x;
        ROWs[i * 64 + ep + 1] = r.y;
    }
    __syncthreads();

    // T = col temp
    for (int idx = tid; idx < 4096; idx += 256) {
        int d = idx >> 6;
        float sd = S[d];
        T[idx] = sd * fmaf(At[d * 36 + k], W1[idx], sd * W5[idx]);
    }
    __syncthreads();

    // COLt[e*32+j]  (packed over e-pairs; j = lane)
    for (int idx = tid; idx < 1024; idx += 256) {
        int ep = (idx >> 5) * 2, j = idx & 31;
        ull acc = pk2(0.f, 0.f);
#pragma unroll 8
        for (int d = 0; d < 64; d++) {
            float a = At[d * 36 + j];
            acc = f2fma(pk2(a, a), *(const ull*)(T + d * 64 + ep), acc);
        }
        float2 r = upk2(acc);
        COLt[ep * 32 + j] = r.x;
        COLt[(ep + 1) * 32 + j] = r.y;
    }
    __syncthreads();

    // final WK[d,e] = a_k[d]*W0 + s[d]*W3
    for (int idx = tid; idx < 4096; idx += 256) {
        int d = idx >> 6;
        WK[idx] = fmaf(At[d * 36 + k], W0[idx], S[d] * W3[idx]);
    }
    __syncthreads();

    int e0 = warp * 8;
    float esum[8] = {0, 0, 0, 0, 0, 0, 0, 0};
    float cbase[8];
#pragma unroll
    for (int t = 0; t < 8; t++) cbase[t] = COLt[(e0 + t) * 32 + lane] + R[e0 + t];

    for (int ig = 0; ig < 8; ig++) {
        int i0 = ig * 4;
        ull acc[4][4];
#pragma unroll
        for (int r = 0; r < 4; r++) {
            const float* rw = ROWs + (i0 + r) * 64 + e0;
#pragma unroll
            for (int p = 0; p < 4; p++)
                acc[r][p] = pk2(cbase[2 * p] + rw[2 * p],
                                cbase[2 * p + 1] + rw[2 * p + 1]);
        }

#pragma unroll 4
        for (int d = 0; d < 64; d++) {
            float aj = At[d * 36 + lane];
            ull aj2 = pk2(aj, aj);
            ull ai01 = *(const ull*)(At + d * 36 + i0);
            ull ai23 = *(const ull*)(At + d * 36 + i0 + 2);
            ull c01 = f2mul(ai01, aj2);
            ull c23 = f2mul(ai23, aj2);
            float2 cA = upk2(c01), cB = upk2(c23);
            ull c0 = pk2(cA.x, cA.x), c1 = pk2(cA.y, cA.y);
            ull c2 = pk2(cB.x, cB.x), c3 = pk2(cB.y, cB.y);
            const ull* wp = (const ull*)(WK + d * 64 + e0);
            ull w0 = wp[0], w1 = wp[1], w2 = wp[2], w3 = wp[3];
            acc[0][0] = f2fma(c0, w0, acc[0][0]);
            acc[0][1] = f2fma(c0, w1, acc[0][1]);
            acc[0][2] = f2fma(c0, w2, acc[0][2]);
            acc[0][3] = f2fma(c0, w3, acc[0][3]);
            acc[1][0] = f2fma(c1, w0, acc[1][0]);
            acc[1][1] = f2fma(c1, w1, acc[1][1]);
            acc[1][2] = f2fma(c1, w2, acc[1][2]);
            acc[1][3] = f2fma(c1, w3, acc[1][3]);
            acc[2][0] = f2fma(c2, w0, acc[2][0]);
            acc[2][1] = f2fma(c2, w1, acc[2][1]);
            acc[2][2] = f2fma(c2, w2, acc[2][2]);
            acc[2][3] = f2fma(c2, w3, acc[2][3]);
            acc[3][0] = f2fma(c3, w0, acc[3][0]);
            acc[3][1] = f2fma(c3, w1, acc[3][1]);
            acc[3][2] = f2fma(c3, w2, acc[3][2]);
            acc[3][3] = f2fma(c3, w3, acc[3][3]);
        }

#pragma unroll
        for (int r = 0; r < 4; r++)
#pragma unroll
            for (int p = 0; p < 4; p++) {
                float2 v = upk2(acc[r][p]);
                esum[2 * p]     += fmaxf(v.x, 0.f);
                esum[2 * p + 1] += fmaxf(v.y, 0.f);
            }
    }

#pragma unroll
    for (int t = 0; t < 8; t++) {
        float v = esum[t];
#pragma unroll
        for (int off = 16; off; off >>= 1)
            v += __shfl_down_sync(0xffffffffu, v, off);
        if (lane == 0) g_part[blockIdx.x * 64 + e0 + t] = v;
    }
}

// ---------------- kernel 5: reduce over k, relu, final linear -----------------
__global__ void __launch_bounds__(512) k_out(const float* __restrict__ out_w,
                                             const float* __restrict__ out_b,
                                             float* __restrict__ out) {
    int tid = threadIdx.x;
    int bb = tid >> 5;
    int lane = tid & 31;
    float a0 = 0.f, a1 = 0.f;
    for (int k = 0; k < 32; k++) {
        const float* p = g_part + (bb * 32 + k) * 64;
        a0 += p[lane];
        a1 += p[lane + 32];
    }
    float x0 = fmaxf(a0 * (1.f / 32768.f), 0.f);
    float x1 = fmaxf(a1 * (1.f / 32768.f), 0.f);
    float acc = x0 * out_w[lane] + x1 * out_w[lane + 32];
#pragma unroll
    for (int off = 16; off; off >>= 1)
        acc += __shfl_down_sync(0xffffffffu, acc, off);
    if (lane == 0) out[bb] = acc + out_b[0];
}

// ---------------- launch ------------------------------------------------------
extern "C" void kernel_launch(void* const* d_in, const int* in_sizes, int n_in,
                              void* d_out, int out_size) {
    const float* x       = (const float*)d_in[0];
    const float* conv1_w = (const float*)d_in[1];
    const float* conv1_b = (const float*)d_in[2];
    const float* conv2_w = (const float*)d_in[3];
    const float* conv2_b = (const float*)d_in[4];
    const float* fc_w    = (const float*)d_in[5];
    const float* fc_b    = (const float*)d_in[6];
    const float* eq_w    = (const float*)d_in[7];
    const float* eq_b    = (const float*)d_in[8];
    const float* out_w   = (const float*)d_in[9];
    const float* out_b   = (const float*)d_in[10];
    float* out = (float*)d_out;

    cudaFuncSetAttribute(k_conv2, cudaFuncAttributeMaxDynamicSharedMemorySize, 99072);
    cudaFuncSetAttribute(k_eq,    cudaFuncAttributeMaxDynamicSharedMemorySize, 42496);

    k_prep<<<16, 256>>>(eq_w);
    k_conv1<<<NIMG, 224>>>(x, conv1_w, conv1_b);
    k_conv2<<<NIMG, 392, 99072>>>(conv2_w, conv2_b);
    k_fc<<<8 * FC_SPLIT, 256>>>(fc_w);
    k_fcred<<<64, 512>>>(fc_b);
    k_eq<<<NIMG, 256, 42496>>>(eq_b);
    k_out<<<1, 512>>>(out_w, out_b, out);
}